// round 1
// baseline (speedup 1.0000x reference)
#include <cuda_runtime.h>
#include <math.h>

#define NPILLARS 120000
#define MPTS 32
#define CIN 9
#define COUT 63
#define WPB 8            // warps (pillars) per block
#define VX 0.16f
#define VY 0.16f
#define X_OFF (0.16f * 0.5f + 0.0f)
#define Y_OFF (0.16f * 0.5f + (-39.68f))
#define BN_EPS 1e-3f

typedef unsigned long long u64;

// Packed f32x2 helpers (sm_103a). ptxas never auto-fuses these from C++.
__device__ __forceinline__ u64 pack2(float lo, float hi) {
    u64 r;
    asm("mov.b64 %0, {%1, %2};" : "=l"(r) : "f"(lo), "f"(hi));
    return r;
}
__device__ __forceinline__ void unpack2(u64 v, float& lo, float& hi) {
    asm("mov.b64 {%0, %1}, %2;" : "=f"(lo), "=f"(hi) : "l"(v));
}
__device__ __forceinline__ u64 ffma2(u64 a, u64 b, u64 c) {
    u64 d;
    asm("fma.rn.f32x2 %0, %1, %2, %3;" : "=l"(d) : "l"(a), "l"(b), "l"(c));
    return d;
}

__global__ __launch_bounds__(WPB * 32)
void pfn_kernel(const float* __restrict__ features,   // (N, M, 4)
                const int*   __restrict__ num_points, // (N)
                const int*   __restrict__ coors,      // (N, 4) [b, z, y, x]
                const float* __restrict__ Wmat,       // (63, 9)
                const float* __restrict__ gamma_,     // (63)
                const float* __restrict__ beta_,      // (63)
                const float* __restrict__ rmean,      // (63)
                const float* __restrict__ rvar,       // (63)
                float*       __restrict__ out)        // (N, 64)
{
    // s9[w][c][m]: point m's feature c, duplicated into both f32x2 halves.
    // Writes (fixed c, lanes m) are coalesced; loop reads (fixed m) broadcast.
    __shared__ u64   s9[WPB][CIN][MPTS];
    __shared__ float sW[CIN][MPTS][2];   // [c][lane] -> (W'[lane][c], W'[lane+32][c])
    __shared__ float sShift[MPTS][2];

    const int tid = threadIdx.x;

    // ---- fold BN into weights (per block; all L2 hits) ----
    if (tid < COUT) {
        float inv = gamma_[tid] * rsqrtf(rvar[tid] + BN_EPS);
        float sh  = beta_[tid] - rmean[tid] * inv;
        int l  = tid & 31;
        int hi = tid >> 5;
        sShift[l][hi] = sh;
        #pragma unroll
        for (int c = 0; c < CIN; c++) sW[c][l][hi] = Wmat[tid * CIN + c] * inv;
    } else if (tid == COUT) {
        // channel 63 does not exist: zero the unused hi slot of lane 31
        sShift[31][1] = 0.0f;
        #pragma unroll
        for (int c = 0; c < CIN; c++) sW[c][31][1] = 0.0f;
    }
    __syncthreads();

    const int w    = tid >> 5;
    const int lane = tid & 31;
    const int n    = blockIdx.x * WPB + w;
    if (n >= NPILLARS) return;

    // ---- per-point raw features ----
    const float4 f4 = reinterpret_cast<const float4*>(features)[n * MPTS + lane];
    const int np = num_points[n];
    const float ox = (float)coors[n * 4 + 3] * VX + X_OFF;
    const float oy = (float)coors[n * 4 + 2] * VY + Y_OFF;

    // centroid: sum over ALL 32 points (padded slots included!), divide by np
    float sx = f4.x, sy = f4.y, sz = f4.z;
    #pragma unroll
    for (int o = 16; o; o >>= 1) {
        sx += __shfl_xor_sync(0xffffffffu, sx, o);
        sy += __shfl_xor_sync(0xffffffffu, sy, o);
        sz += __shfl_xor_sync(0xffffffffu, sz, o);
    }
    const float rnp = 1.0f / (float)np;
    const float mx = sx * rnp, my = sy * rnp, mz = sz * rnp;

    // store this lane's 9-dim feature, duplicated-packed
    s9[w][0][lane] = pack2(f4.x, f4.x);
    s9[w][1][lane] = pack2(f4.y, f4.y);
    s9[w][2][lane] = pack2(f4.z, f4.z);
    s9[w][3][lane] = pack2(f4.w, f4.w);
    s9[w][4][lane] = pack2(f4.x - mx, f4.x - mx);
    s9[w][5][lane] = pack2(f4.y - my, f4.y - my);
    s9[w][6][lane] = pack2(f4.z - mz, f4.z - mz);
    s9[w][7][lane] = pack2(f4.x - ox, f4.x - ox);
    s9[w][8][lane] = pack2(f4.y - oy, f4.y - oy);
    __syncwarp();

    // ---- per-lane channel pair (u0 = lane, u1 = lane + 32) ----
    u64 w2[CIN];
    #pragma unroll
    for (int c = 0; c < CIN; c++)
        w2[c] = *reinterpret_cast<const u64*>(&sW[c][lane][0]);
    const u64 sh2 = *reinterpret_cast<const u64*>(&sShift[lane][0]);
    float sh_lo, sh_hi;
    unpack2(sh2, sh_lo, sh_hi);

    float acc_lo = -3.4e38f, acc_hi = -3.4e38f;
    // loop only over valid points (uniform trip count within the warp)
    for (int m = 0; m < np; m++) {
        u64 v = sh2;
        #pragma unroll
        for (int c = 0; c < CIN; c++)
            v = ffma2(s9[w][c][m], w2[c], v);  // LDS.64 broadcast + FFMA2
        float lo, hi;
        unpack2(v, lo, hi);
        acc_lo = fmaxf(acc_lo, lo);
        acc_hi = fmaxf(acc_hi, hi);
    }
    // masked points contribute exactly `shift` (zero 9-vector through linear)
    if (np < MPTS) {
        acc_lo = fmaxf(acc_lo, sh_lo);
        acc_hi = fmaxf(acc_hi, sh_hi);
    }
    // relu after max (relu is monotone)
    acc_lo = fmaxf(acc_lo, 0.0f);
    acc_hi = fmaxf(acc_hi, 0.0f);

    float* o = out + (size_t)n * 64;
    o[lane] = acc_lo;                       // channels 0..31
    if (lane < 31) o[32 + lane] = acc_hi;   // channels 32..62
    else           o[63] = (float)np;       // appended num_points
}

extern "C" void kernel_launch(void* const* d_in, const int* in_sizes, int n_in,
                              void* d_out, int out_size)
{
    const float* features   = (const float*)d_in[0];
    const int*   num_points = (const int*)  d_in[1];
    const int*   coors      = (const int*)  d_in[2];
    const float* Wmat       = (const float*)d_in[3];
    const float* gamma_     = (const float*)d_in[4];
    const float* beta_      = (const float*)d_in[5];
    const float* rmean      = (const float*)d_in[6];
    const float* rvar       = (const float*)d_in[7];
    float*       out        = (float*)d_out;

    const int blocks = (NPILLARS + WPB - 1) / WPB;  // 15000
    pfn_kernel<<<blocks, WPB * 32>>>(features, num_points, coors, Wmat,
                                     gamma_, beta_, rmean, rvar, out);
}

// round 2
// speedup vs baseline: 1.5470x; 1.5470x over previous
#include <cuda_runtime.h>
#include <math.h>

#define NPILLARS 120000
#define MPTS 32
#define CIN 9
#define COUT 63
#define WPB 8            // warps (pillars) per block
#define VX 0.16f
#define VY 0.16f
#define X_OFF (0.16f * 0.5f + 0.0f)
#define Y_OFF (0.16f * 0.5f + (-39.68f))
#define BN_EPS 1e-3f

typedef unsigned long long u64;

__device__ __forceinline__ u64 pack2(float lo, float hi) {
    u64 r;
    asm("mov.b64 %0, {%1, %2};" : "=l"(r) : "f"(lo), "f"(hi));
    return r;
}
__device__ __forceinline__ void unpack2(u64 v, float& lo, float& hi) {
    asm("mov.b64 {%0, %1}, %2;" : "=f"(lo), "=f"(hi) : "l"(v));
}
__device__ __forceinline__ u64 ffma2(u64 a, u64 b, u64 c) {
    u64 d;
    asm("fma.rn.f32x2 %0, %1, %2, %3;" : "=l"(d) : "l"(a), "l"(b), "l"(c));
    return d;
}
// 16B shared load -> two packed f32x2 (features of 4 consecutive points)
__device__ __forceinline__ void lds2(u64& a, u64& b, unsigned addr) {
    asm("ld.shared.v2.b64 {%0, %1}, [%2];" : "=l"(a), "=l"(b) : "r"(addr));
}

__global__ __launch_bounds__(WPB * 32)
void pfn_kernel(const float* __restrict__ features,   // (N, M, 4)
                const int*   __restrict__ num_points, // (N)
                const int*   __restrict__ coors,      // (N, 4) [b, z, y, x]
                const float* __restrict__ Wmat,       // (63, 9)
                const float* __restrict__ gamma_,     // (63)
                const float* __restrict__ beta_,      // (63)
                const float* __restrict__ rmean,      // (63)
                const float* __restrict__ rvar,       // (63)
                float*       __restrict__ out)        // (N, 64)
{
    // sF[w][c][m]: feature c of point m (plain f32). Row = 128B, 16B-aligned,
    // so a v2.b64 load at [c][4j] broadcasts a quad of points conflict-free.
    __shared__ __align__(16) float sF[WPB][CIN][MPTS];
    __shared__ u64   sWd[CIN][64];   // duplicated-packed folded weights (W',W')
    __shared__ float sSh[64];        // folded BN shift (slot 63 = 0)

    const int tid = threadIdx.x;

    if (tid < 64) {
        float inv = 0.0f, sh = 0.0f;
        if (tid < COUT) {
            inv = gamma_[tid] * rsqrtf(rvar[tid] + BN_EPS);
            sh  = beta_[tid] - rmean[tid] * inv;
        }
        sSh[tid] = sh;
        #pragma unroll
        for (int c = 0; c < CIN; c++) {
            float wv = (tid < COUT) ? Wmat[tid * CIN + c] * inv : 0.0f;
            sWd[c][tid] = pack2(wv, wv);
        }
    }
    __syncthreads();

    const int w    = tid >> 5;
    const int lane = tid & 31;
    const int n    = blockIdx.x * WPB + w;   // grid covers exactly NPILLARS

    const float4 f4 = reinterpret_cast<const float4*>(features)[n * MPTS + lane];
    const int np = num_points[n];
    const float ox = (float)coors[n * 4 + 3] * VX + X_OFF;
    const float oy = (float)coors[n * 4 + 2] * VY + Y_OFF;

    // centroid: sum over ALL 32 slots (reference sums padded garbage too), / np
    float sx = f4.x, sy = f4.y, sz = f4.z;
    #pragma unroll
    for (int o = 16; o; o >>= 1) {
        sx += __shfl_xor_sync(0xffffffffu, sx, o);
        sy += __shfl_xor_sync(0xffffffffu, sy, o);
        sz += __shfl_xor_sync(0xffffffffu, sz, o);
    }
    const float rnp = 1.0f / (float)np;
    const float mx = sx * rnp, my = sy * rnp, mz = sz * rnp;

    // write this lane's 9-dim feature; zero padded slots (-> exact `shift`)
    const bool valid = lane < np;
    sF[w][0][lane] = valid ? f4.x : 0.0f;
    sF[w][1][lane] = valid ? f4.y : 0.0f;
    sF[w][2][lane] = valid ? f4.z : 0.0f;
    sF[w][3][lane] = valid ? f4.w : 0.0f;
    sF[w][4][lane] = valid ? (f4.x - mx) : 0.0f;
    sF[w][5][lane] = valid ? (f4.y - my) : 0.0f;
    sF[w][6][lane] = valid ? (f4.z - mz) : 0.0f;
    sF[w][7][lane] = valid ? (f4.x - ox) : 0.0f;
    sF[w][8][lane] = valid ? (f4.y - oy) : 0.0f;
    __syncwarp();

    // lane owns channels u=lane and u+32; weights duplicated-packed in regs
    u64 w2l[CIN], w2h[CIN];
    #pragma unroll
    for (int c = 0; c < CIN; c++) {
        w2l[c] = sWd[c][lane];
        w2h[c] = sWd[c][lane + 32];
    }
    const float sh_lo = sSh[lane];
    const float sh_hi = sSh[lane + 32];
    const u64 sh2l = pack2(sh_lo, sh_lo);
    const u64 sh2h = pack2(sh_hi, sh_hi);

    const unsigned fbase =
        (unsigned)__cvta_generic_to_shared(&sF[w][0][0]);

    float accl = -3.4e38f, acch = -3.4e38f;
    const int nq = (np + 3) >> 2;           // quads of points
    for (int j = 0; j < nq; j++) {
        const unsigned addr = fbase + j * 16;
        u64 a01, a23;
        lds2(a01, a23, addr);
        u64 v01l = ffma2(a01, w2l[0], sh2l);
        u64 v23l = ffma2(a23, w2l[0], sh2l);
        u64 v01h = ffma2(a01, w2h[0], sh2h);
        u64 v23h = ffma2(a23, w2h[0], sh2h);
        #pragma unroll
        for (int c = 1; c < CIN; c++) {
            lds2(a01, a23, addr + c * (MPTS * 4));
            v01l = ffma2(a01, w2l[c], v01l);
            v23l = ffma2(a23, w2l[c], v23l);
            v01h = ffma2(a01, w2h[c], v01h);
            v23h = ffma2(a23, w2h[c], v23h);
        }
        float x0, x1;
        unpack2(v01l, x0, x1); accl = fmaxf(accl, fmaxf(x0, x1));
        unpack2(v23l, x0, x1); accl = fmaxf(accl, fmaxf(x0, x1));
        unpack2(v01h, x0, x1); acch = fmaxf(acch, fmaxf(x0, x1));
        unpack2(v23h, x0, x1); acch = fmaxf(acch, fmaxf(x0, x1));
    }
    // padded points contribute exactly `shift` (only legal when np < 32)
    if (np < MPTS) {
        accl = fmaxf(accl, sh_lo);
        acch = fmaxf(acch, sh_hi);
    }
    accl = fmaxf(accl, 0.0f);   // relu after max (monotone)
    acch = fmaxf(acch, 0.0f);

    float* o = out + (size_t)n * 64;
    o[lane] = accl;                       // channels 0..31
    if (lane < 31) o[32 + lane] = acch;   // channels 32..62
    else           o[63] = (float)np;     // appended num_points
}

extern "C" void kernel_launch(void* const* d_in, const int* in_sizes, int n_in,
                              void* d_out, int out_size)
{
    const float* features   = (const float*)d_in[0];
    const int*   num_points = (const int*)  d_in[1];
    const int*   coors      = (const int*)  d_in[2];
    const float* Wmat       = (const float*)d_in[3];
    const float* gamma_     = (const float*)d_in[4];
    const float* beta_      = (const float*)d_in[5];
    const float* rmean      = (const float*)d_in[6];
    const float* rvar       = (const float*)d_in[7];
    float*       out        = (float*)d_out;

    const int blocks = NPILLARS / WPB;   // 15000, exact
    pfn_kernel<<<blocks, WPB * 32>>>(features, num_points, coors, Wmat,
                                     gamma_, beta_, rmean, rvar, out);
}

// round 3
// speedup vs baseline: 2.9213x; 1.8884x over previous
#include <cuda_runtime.h>
#include <math.h>

#define NPILLARS 120000
#define MPTS 32
#define CIN 9
#define COUT 63
#define WPB 8            // warps (pillars) per block
#define VX 0.16f
#define VY 0.16f
#define X_OFF (0.16f * 0.5f + 0.0f)
#define Y_OFF (0.16f * 0.5f + (-39.68f))
#define BN_EPS 1e-3f

typedef unsigned long long u64;

__device__ __forceinline__ u64 pack2(float lo, float hi) {
    u64 r;
    asm("mov.b64 %0, {%1, %2};" : "=l"(r) : "f"(lo), "f"(hi));
    return r;
}
__device__ __forceinline__ void unpack2(u64 v, float& lo, float& hi) {
    asm("mov.b64 {%0, %1}, %2;" : "=f"(lo), "=f"(hi) : "l"(v));
}
__device__ __forceinline__ u64 ffma2(u64 a, u64 b, u64 c) {
    u64 d;
    asm("fma.rn.f32x2 %0, %1, %2, %3;" : "=l"(d) : "l"(a), "l"(b), "l"(c));
    return d;
}
// 16B shared load -> two packed f32x2 (one channel of 4 consecutive points)
__device__ __forceinline__ void lds2(u64& a, u64& b, unsigned addr) {
    asm("ld.shared.v2.b64 {%0, %1}, [%2];" : "=l"(a), "=l"(b) : "r"(addr));
}

__global__ __launch_bounds__(WPB * 32)
void pfn_kernel(const float* __restrict__ features,   // (N, M, 4)
                const int*   __restrict__ num_points, // (N)
                const int*   __restrict__ coors,      // (N, 4) [b, z, y, x]
                const float* __restrict__ Wmat,       // (63, 9)
                const float* __restrict__ gamma_,     // (63)
                const float* __restrict__ beta_,      // (63)
                const float* __restrict__ rmean,      // (63)
                const float* __restrict__ rvar,       // (63)
                float*       __restrict__ out)        // (N, 64)
{
    // Raw point coords only: sF[w][c][m], c in {x,y,z,w}. Rows = 128B.
    __shared__ __align__(16) float sF[WPB][4][MPTS];
    __shared__ float sWt[4][64];    // combined weights: Wt0=W0+W4+W7, Wt1=W1+W5+W8, Wt2=W2+W6, Wt3=W3
    __shared__ float sWo[5][64];    // original W'[u][4..8] (for per-pillar bias fold)
    __shared__ float sSh[64];       // folded BN shift (slot 63 = 0)

    const int tid = threadIdx.x;

    if (tid < 64) {
        float inv = 0.0f, sh = 0.0f;
        float wp[CIN];
        #pragma unroll
        for (int c = 0; c < CIN; c++) wp[c] = 0.0f;
        if (tid < COUT) {
            inv = gamma_[tid] * rsqrtf(rvar[tid] + BN_EPS);
            sh  = beta_[tid] - rmean[tid] * inv;
            #pragma unroll
            for (int c = 0; c < CIN; c++) wp[c] = Wmat[tid * CIN + c] * inv;
        }
        sSh[tid]    = sh;
        sWt[0][tid] = wp[0] + wp[4] + wp[7];
        sWt[1][tid] = wp[1] + wp[5] + wp[8];
        sWt[2][tid] = wp[2] + wp[6];
        sWt[3][tid] = wp[3];
        #pragma unroll
        for (int c = 0; c < 5; c++) sWo[c][tid] = wp[4 + c];
    }
    __syncthreads();

    const int w    = tid >> 5;
    const int lane = tid & 31;
    const int n    = blockIdx.x * WPB + w;   // grid covers exactly NPILLARS

    const float4 f4 = reinterpret_cast<const float4*>(features)[n * MPTS + lane];
    const int np = num_points[n];
    const float ox = (float)coors[n * 4 + 3] * VX + X_OFF;
    const float oy = (float)coors[n * 4 + 2] * VY + Y_OFF;

    // centroid: reference sums ALL 32 slots (incl. padded garbage), / np
    float sx = f4.x, sy = f4.y, sz = f4.z;
    #pragma unroll
    for (int o = 16; o; o >>= 1) {
        sx += __shfl_xor_sync(0xffffffffu, sx, o);
        sy += __shfl_xor_sync(0xffffffffu, sy, o);
        sz += __shfl_xor_sync(0xffffffffu, sz, o);
    }
    const float rnp = 1.0f / (float)np;
    const float mx = sx * rnp, my = sy * rnp, mz = sz * rnp;

    // padded slots get point 0's coords -> over-read quads reproduce an
    // existing max candidate exactly (np >= 1 guaranteed)
    const float p0x = __shfl_sync(0xffffffffu, f4.x, 0);
    const float p0y = __shfl_sync(0xffffffffu, f4.y, 0);
    const float p0z = __shfl_sync(0xffffffffu, f4.z, 0);
    const float p0w = __shfl_sync(0xffffffffu, f4.w, 0);
    const bool valid = lane < np;
    sF[w][0][lane] = valid ? f4.x : p0x;
    sF[w][1][lane] = valid ? f4.y : p0y;
    sF[w][2][lane] = valid ? f4.z : p0z;
    sF[w][3][lane] = valid ? f4.w : p0w;
    __syncwarp();

    // lane owns channels u=lane and u+32
    const int ul = lane, uh = lane + 32;
    const u64 w0l = pack2(sWt[0][ul], sWt[0][ul]);
    const u64 w1l = pack2(sWt[1][ul], sWt[1][ul]);
    const u64 w2l = pack2(sWt[2][ul], sWt[2][ul]);
    const u64 w3l = pack2(sWt[3][ul], sWt[3][ul]);
    const u64 w0h = pack2(sWt[0][uh], sWt[0][uh]);
    const u64 w1h = pack2(sWt[1][uh], sWt[1][uh]);
    const u64 w2h = pack2(sWt[2][uh], sWt[2][uh]);
    const u64 w3h = pack2(sWt[3][uh], sWt[3][uh]);

    const float sh_lo = sSh[ul], sh_hi = sSh[uh];
    // per-pillar bias: b[u] = sh[u] - mx*W4 - my*W5 - mz*W6 - ox*W7 - oy*W8
    float b_lo = sh_lo - mx * sWo[0][ul] - my * sWo[1][ul] - mz * sWo[2][ul]
                       - ox * sWo[3][ul] - oy * sWo[4][ul];
    float b_hi = sh_hi - mx * sWo[0][uh] - my * sWo[1][uh] - mz * sWo[2][uh]
                       - ox * sWo[3][uh] - oy * sWo[4][uh];
    const u64 b2l = pack2(b_lo, b_lo);
    const u64 b2h = pack2(b_hi, b_hi);

    const unsigned fbase = (unsigned)__cvta_generic_to_shared(&sF[w][0][0]);

    float accl = -3.4e38f, acch = -3.4e38f;
    const int nq = (np + 3) >> 2;            // quads of points
    for (int j = 0; j < nq; j++) {
        const unsigned addr = fbase + j * 16;
        u64 x01, x23, y01, y23, z01, z23, q01, q23;
        lds2(x01, x23, addr);
        lds2(y01, y23, addr + 128);
        lds2(z01, z23, addr + 256);
        lds2(q01, q23, addr + 384);

        u64 v01l = ffma2(x01, w0l, b2l);
        u64 v23l = ffma2(x23, w0l, b2l);
        u64 v01h = ffma2(x01, w0h, b2h);
        u64 v23h = ffma2(x23, w0h, b2h);
        v01l = ffma2(y01, w1l, v01l);
        v23l = ffma2(y23, w1l, v23l);
        v01h = ffma2(y01, w1h, v01h);
        v23h = ffma2(y23, w1h, v23h);
        v01l = ffma2(z01, w2l, v01l);
        v23l = ffma2(z23, w2l, v23l);
        v01h = ffma2(z01, w2h, v01h);
        v23h = ffma2(z23, w2h, v23h);
        v01l = ffma2(q01, w3l, v01l);
        v23l = ffma2(q23, w3l, v23l);
        v01h = ffma2(q01, w3h, v01h);
        v23h = ffma2(q23, w3h, v23h);

        float a0, a1;
        unpack2(v01l, a0, a1); accl = fmaxf(accl, fmaxf(a0, a1));
        unpack2(v23l, a0, a1); accl = fmaxf(accl, fmaxf(a0, a1));
        unpack2(v01h, a0, a1); acch = fmaxf(acch, fmaxf(a0, a1));
        unpack2(v23h, a0, a1); acch = fmaxf(acch, fmaxf(a0, a1));
    }
    // padded points contribute exactly `shift` when np < 32 (reference masks to 0)
    if (np < MPTS) {
        accl = fmaxf(accl, sh_lo);
        acch = fmaxf(acch, sh_hi);
    }
    accl = fmaxf(accl, 0.0f);   // relu after max (monotone)
    acch = fmaxf(acch, 0.0f);

    float* o = out + (size_t)n * 64;
    o[lane] = accl;                       // channels 0..31
    if (lane < 31) o[32 + lane] = acch;   // channels 32..62
    else           o[63] = (float)np;     // appended num_points
}

extern "C" void kernel_launch(void* const* d_in, const int* in_sizes, int n_in,
                              void* d_out, int out_size)
{
    const float* features   = (const float*)d_in[0];
    const int*   num_points = (const int*)  d_in[1];
    const int*   coors      = (const int*)  d_in[2];
    const float* Wmat       = (const float*)d_in[3];
    const float* gamma_     = (const float*)d_in[4];
    const float* beta_      = (const float*)d_in[5];
    const float* rmean      = (const float*)d_in[6];
    const float* rvar       = (const float*)d_in[7];
    float*       out        = (float*)d_out;

    const int blocks = NPILLARS / WPB;   // 15000, exact
    pfn_kernel<<<blocks, WPB * 32>>>(features, num_points, coors, Wmat,
                                     gamma_, beta_, rmean, rvar, out);
}

// round 6
// speedup vs baseline: 3.4314x; 1.1746x over previous
#include <cuda_runtime.h>
#include <math.h>

#define NPILLARS 120000
#define MPTS 32
#define CIN 9
#define COUT 63
#define WPB 8              // warps per block
#define PPW 10             // pillars per warp
#define TOTWARPS (NPILLARS / PPW)   // 12000
#define NBLOCKS  (TOTWARPS / WPB)   // 1500
#define VX 0.16f
#define VY 0.16f
#define X_OFF (0.16f * 0.5f + 0.0f)
#define Y_OFF (0.16f * 0.5f + (-39.68f))
#define BN_EPS 1e-3f

typedef unsigned long long u64;

__device__ __forceinline__ u64 pack2(float lo, float hi) {
    u64 r;
    asm("mov.b64 %0, {%1, %2};" : "=l"(r) : "f"(lo), "f"(hi));
    return r;
}
__device__ __forceinline__ void unpack2(u64 v, float& lo, float& hi) {
    asm("mov.b64 {%0, %1}, %2;" : "=f"(lo), "=f"(hi) : "l"(v));
}
__device__ __forceinline__ u64 ffma2(u64 a, u64 b, u64 c) {
    u64 d;
    asm("fma.rn.f32x2 %0, %1, %2, %3;" : "=l"(d) : "l"(a), "l"(b), "l"(c));
    return d;
}
// 16B shared load -> two packed f32x2 (one channel of 4 consecutive points)
__device__ __forceinline__ void lds2(u64& a, u64& b, unsigned addr) {
    asm("ld.shared.v2.b64 {%0, %1}, [%2];" : "=l"(a), "=l"(b) : "r"(addr));
}

__global__ __launch_bounds__(WPB * 32)
void pfn_kernel(const float* __restrict__ features,   // (N, M, 4)
                const int*   __restrict__ num_points, // (N)
                const int*   __restrict__ coors,      // (N, 4) [b, z, y, x]
                const float* __restrict__ Wmat,       // (63, 9)
                const float* __restrict__ gamma_,     // (63)
                const float* __restrict__ beta_,      // (63)
                const float* __restrict__ rmean,      // (63)
                const float* __restrict__ rvar,       // (63)
                float*       __restrict__ out)        // (N, 64)
{
    __shared__ __align__(16) float sF[WPB][4][MPTS];  // raw coords per warp
    __shared__ float sWt[4][64];   // Wt0=W0+W4+W7, Wt1=W1+W5+W8, Wt2=W2+W6, Wt3=W3
    __shared__ float sWo[5][64];   // W'[u][4..8] for per-pillar bias fold
    __shared__ float sSh[64];      // folded BN shift (slot 63 = 0)

    const int tid = threadIdx.x;

    if (tid < 64) {
        float inv = 0.0f, sh = 0.0f;
        float wp[CIN];
        #pragma unroll
        for (int c = 0; c < CIN; c++) wp[c] = 0.0f;
        if (tid < COUT) {
            inv = gamma_[tid] * rsqrtf(rvar[tid] + BN_EPS);
            sh  = beta_[tid] - rmean[tid] * inv;
            #pragma unroll
            for (int c = 0; c < CIN; c++) wp[c] = Wmat[tid * CIN + c] * inv;
        }
        sSh[tid]    = sh;
        sWt[0][tid] = wp[0] + wp[4] + wp[7];
        sWt[1][tid] = wp[1] + wp[5] + wp[8];
        sWt[2][tid] = wp[2] + wp[6];
        sWt[3][tid] = wp[3];
        #pragma unroll
        for (int c = 0; c < 5; c++) sWo[c][tid] = wp[4 + c];
    }
    __syncthreads();

    const int w    = tid >> 5;
    const int lane = tid & 31;
    const int gw   = blockIdx.x * WPB + w;   // global warp id, 0..11999

    // ---- persistent per-warp registers (loaded ONCE per warp lifetime) ----
    const int ul = lane, uh = lane + 32;
    float t;
    t = sWt[0][ul]; const u64 w0l = pack2(t, t);
    t = sWt[1][ul]; const u64 w1l = pack2(t, t);
    t = sWt[2][ul]; const u64 w2l = pack2(t, t);
    t = sWt[3][ul]; const u64 w3l = pack2(t, t);
    t = sWt[0][uh]; const u64 w0h = pack2(t, t);
    t = sWt[1][uh]; const u64 w1h = pack2(t, t);
    t = sWt[2][uh]; const u64 w2h = pack2(t, t);
    t = sWt[3][uh]; const u64 w3h = pack2(t, t);
    const float wo0l = sWo[0][ul], wo1l = sWo[1][ul], wo2l = sWo[2][ul],
                wo3l = sWo[3][ul], wo4l = sWo[4][ul];
    const float wo0h = sWo[0][uh], wo1h = sWo[1][uh], wo2h = sWo[2][uh],
                wo3h = sWo[3][uh], wo4h = sWo[4][uh];
    const float sh_lo = sSh[ul], sh_hi = sSh[uh];

    const unsigned fbase = (unsigned)__cvta_generic_to_shared(&sF[w][0][0]);
    const float4* __restrict__ feat4 = reinterpret_cast<const float4*>(features);

    // ---- first pillar's loads ----
    int n = gw;
    float4 f4 = feat4[n * MPTS + lane];
    int np = num_points[n];
    int2 yx = *reinterpret_cast<const int2*>(coors + n * 4 + 2);  // {y, x}

    #pragma unroll 1
    for (int k = 0; k < PPW; k++) {
        // prefetch next pillar while processing this one
        float4 f4n; int npn; int2 yxn;
        if (k + 1 < PPW) {
            const int n2 = n + TOTWARPS;
            f4n = feat4[n2 * MPTS + lane];
            npn = num_points[n2];
            yxn = *reinterpret_cast<const int2*>(coors + n2 * 4 + 2);
        }

        const float ox = (float)yx.y * VX + X_OFF;
        const float oy = (float)yx.x * VY + Y_OFF;

        // centroid: reference sums ALL 32 slots (incl. padded garbage), / np
        float sx = f4.x, sy = f4.y, sz = f4.z;
        #pragma unroll
        for (int o = 16; o; o >>= 1) {
            sx += __shfl_xor_sync(0xffffffffu, sx, o);
            sy += __shfl_xor_sync(0xffffffffu, sy, o);
            sz += __shfl_xor_sync(0xffffffffu, sz, o);
        }
        const float rnp = 1.0f / (float)np;
        const float mx = sx * rnp, my = sy * rnp, mz = sz * rnp;

        // padded slots get point 0's coords -> over-read quads reproduce an
        // existing max candidate exactly (np >= 1 guaranteed)
        const float p0x = __shfl_sync(0xffffffffu, f4.x, 0);
        const float p0y = __shfl_sync(0xffffffffu, f4.y, 0);
        const float p0z = __shfl_sync(0xffffffffu, f4.z, 0);
        const float p0w = __shfl_sync(0xffffffffu, f4.w, 0);
        const bool valid = lane < np;
        sF[w][0][lane] = valid ? f4.x : p0x;
        sF[w][1][lane] = valid ? f4.y : p0y;
        sF[w][2][lane] = valid ? f4.z : p0z;
        sF[w][3][lane] = valid ? f4.w : p0w;
        __syncwarp();

        // per-pillar bias: b[u] = sh[u] - mx*W4 - my*W5 - mz*W6 - ox*W7 - oy*W8
        float b_lo = sh_lo - mx * wo0l - my * wo1l - mz * wo2l - ox * wo3l - oy * wo4l;
        float b_hi = sh_hi - mx * wo0h - my * wo1h - mz * wo2h - ox * wo3h - oy * wo4h;
        const u64 b2l = pack2(b_lo, b_lo);
        const u64 b2h = pack2(b_hi, b_hi);

        float al0 = -3.4e38f, al1 = -3.4e38f, ah0 = -3.4e38f, ah1 = -3.4e38f;
        const int nq = (np + 3) >> 2;            // quads of points
        for (int j = 0; j < nq; j++) {
            const unsigned addr = fbase + j * 16;
            u64 x01, x23, y01, y23, z01, z23, q01, q23;
            lds2(x01, x23, addr);
            lds2(y01, y23, addr + 128);
            lds2(z01, z23, addr + 256);
            lds2(q01, q23, addr + 384);

            u64 v01l = ffma2(x01, w0l, b2l);
            u64 v23l = ffma2(x23, w0l, b2l);
            u64 v01h = ffma2(x01, w0h, b2h);
            u64 v23h = ffma2(x23, w0h, b2h);
            v01l = ffma2(y01, w1l, v01l);
            v23l = ffma2(y23, w1l, v23l);
            v01h = ffma2(y01, w1h, v01h);
            v23h = ffma2(y23, w1h, v23h);
            v01l = ffma2(z01, w2l, v01l);
            v23l = ffma2(z23, w2l, v23l);
            v01h = ffma2(z01, w2h, v01h);
            v23h = ffma2(z23, w2h, v23h);
            v01l = ffma2(q01, w3l, v01l);
            v23l = ffma2(q23, w3l, v23l);
            v01h = ffma2(q01, w3h, v01h);
            v23h = ffma2(q23, w3h, v23h);

            float a0, a1;
            unpack2(v01l, a0, a1); al0 = fmaxf(al0, a0); al1 = fmaxf(al1, a1);
            unpack2(v23l, a0, a1); al0 = fmaxf(al0, a0); al1 = fmaxf(al1, a1);
            unpack2(v01h, a0, a1); ah0 = fmaxf(ah0, a0); ah1 = fmaxf(ah1, a1);
            unpack2(v23h, a0, a1); ah0 = fmaxf(ah0, a0); ah1 = fmaxf(ah1, a1);
        }
        float accl = fmaxf(al0, al1);
        float acch = fmaxf(ah0, ah1);
        // padded points contribute exactly `shift` when np < 32
        if (np < MPTS) {
            accl = fmaxf(accl, sh_lo);
            acch = fmaxf(acch, sh_hi);
        }
        accl = fmaxf(accl, 0.0f);   // relu after max (monotone)
        acch = fmaxf(acch, 0.0f);

        float* o = out + (size_t)n * 64;
        o[lane] = accl;                       // channels 0..31
        if (lane < 31) o[32 + lane] = acch;   // channels 32..62
        else           o[63] = (float)np;     // appended num_points

        __syncwarp();   // all lanes done with sF before next pillar overwrites
        n += TOTWARPS;
        f4 = f4n; np = npn; yx = yxn;
    }
}

extern "C" void kernel_launch(void* const* d_in, const int* in_sizes, int n_in,
                              void* d_out, int out_size)
{
    const float* features   = (const float*)d_in[0];
    const int*   num_points = (const int*)  d_in[1];
    const int*   coors      = (const int*)  d_in[2];
    const float* Wmat       = (const float*)d_in[3];
    const float* gamma_     = (const float*)d_in[4];
    const float* beta_      = (const float*)d_in[5];
    const float* rmean      = (const float*)d_in[6];
    const float* rvar       = (const float*)d_in[7];
    float*       out        = (float*)d_out;

    pfn_kernel<<<NBLOCKS, WPB * 32>>>(features, num_points, coors, Wmat,
                                      gamma_, beta_, rmean, rvar, out);
}

// round 10
// speedup vs baseline: 3.7112x; 1.0816x over previous
#include <cuda_runtime.h>
#include <math.h>

#define NPILLARS 120000
#define MPTS 32
#define CIN 9
#define COUT 63
#define WPB 8              // warps per block
#define PPW 10             // pillars per warp
#define TOTWARPS (NPILLARS / PPW)   // 12000
#define NBLOCKS  (TOTWARPS / WPB)   // 1500
#define VX 0.16f
#define VY 0.16f
#define X_OFF (0.16f * 0.5f + 0.0f)
#define Y_OFF (0.16f * 0.5f + (-39.68f))
#define BN_EPS 1e-3f
#define FPSCALE 1048576.0f           // 2^20 fixed-point scale for centroid
#define INV_FPSCALE (1.0f / 1048576.0f)

typedef unsigned long long u64;

__device__ __forceinline__ u64 pack2(float lo, float hi) {
    u64 r;
    asm("mov.b64 %0, {%1, %2};" : "=l"(r) : "f"(lo), "f"(hi));
    return r;
}
__device__ __forceinline__ void unpack2(u64 v, float& lo, float& hi) {
    asm("mov.b64 {%0, %1}, %2;" : "=f"(lo), "=f"(hi) : "l"(v));
}
__device__ __forceinline__ u64 ffma2(u64 a, u64 b, u64 c) {
    u64 d;
    asm("fma.rn.f32x2 %0, %1, %2, %3;" : "=l"(d) : "l"(a), "l"(b), "l"(c));
    return d;
}
__device__ __forceinline__ u64 fmul2(u64 a, u64 b) {
    u64 d;
    asm("mul.rn.f32x2 %0, %1, %2;" : "=l"(d) : "l"(a), "l"(b));
    return d;
}
// integer warp reduction (sm_80+, legal on sm_103a)
__device__ __forceinline__ int redux_add_s32(int v) {
    int r;
    asm("redux.sync.add.s32 %0, %1, 0xffffffff;" : "=r"(r) : "r"(v));
    return r;
}
// 16B shared load -> two packed f32x2 (one channel of 4 consecutive points)
__device__ __forceinline__ void lds2(u64& a, u64& b, unsigned addr) {
    asm("ld.shared.v2.b64 {%0, %1}, [%2];" : "=l"(a), "=l"(b) : "r"(addr));
}

__global__ __launch_bounds__(WPB * 32)
void pfn_kernel(const float* __restrict__ features,   // (N, M, 4)
                const int*   __restrict__ num_points, // (N)
                const int*   __restrict__ coors,      // (N, 4) [b, z, y, x]
                const float* __restrict__ Wmat,       // (63, 9)
                const float* __restrict__ gamma_,     // (63)
                const float* __restrict__ beta_,      // (63)
                const float* __restrict__ rmean,      // (63)
                const float* __restrict__ rvar,       // (63)
                float*       __restrict__ out)        // (N, 64)
{
    __shared__ __align__(16) float sF[WPB][4][MPTS];  // raw coords per warp
    __shared__ float sWt[4][64];   // Wt0=W0+W4+W7, Wt1=W1+W5+W8, Wt2=W2+W6, Wt3=W3
    __shared__ float sWo[5][64];   // W'[u][4..8] for per-pillar bias fold
    __shared__ float sSh[64];      // folded BN shift (slot 63 = 0)

    const int tid = threadIdx.x;

    if (tid < 64) {
        float inv = 0.0f, sh = 0.0f;
        float wp[CIN];
        #pragma unroll
        for (int c = 0; c < CIN; c++) wp[c] = 0.0f;
        if (tid < COUT) {
            inv = gamma_[tid] * rsqrtf(rvar[tid] + BN_EPS);
            sh  = beta_[tid] - rmean[tid] * inv;
            #pragma unroll
            for (int c = 0; c < CIN; c++) wp[c] = Wmat[tid * CIN + c] * inv;
        }
        sSh[tid]    = sh;
        sWt[0][tid] = wp[0] + wp[4] + wp[7];
        sWt[1][tid] = wp[1] + wp[5] + wp[8];
        sWt[2][tid] = wp[2] + wp[6];
        sWt[3][tid] = wp[3];
        #pragma unroll
        for (int c = 0; c < 5; c++) sWo[c][tid] = wp[4 + c];
    }
    __syncthreads();

    const int w    = tid >> 5;
    const int lane = tid & 31;
    const int gw   = blockIdx.x * WPB + w;   // global warp id, 0..11999

    // ---- persistent per-warp registers (loaded ONCE per warp lifetime) ----
    const int ul = lane, uh = lane + 32;
    float t;
    t = sWt[0][ul]; const u64 w0l = pack2(t, t);
    t = sWt[1][ul]; const u64 w1l = pack2(t, t);
    t = sWt[2][ul]; const u64 w2l = pack2(t, t);
    t = sWt[3][ul]; const u64 w3l = pack2(t, t);
    t = sWt[0][uh]; const u64 w0h = pack2(t, t);
    t = sWt[1][uh]; const u64 w1h = pack2(t, t);
    t = sWt[2][uh]; const u64 w2h = pack2(t, t);
    t = sWt[3][uh]; const u64 w3h = pack2(t, t);
    // bias-fold weights packed (lo-channel, hi-channel) for 2-wide fma chain
    const u64 wop0 = pack2(sWo[0][ul], sWo[0][uh]);
    const u64 wop1 = pack2(sWo[1][ul], sWo[1][uh]);
    const u64 wop2 = pack2(sWo[2][ul], sWo[2][uh]);
    const u64 wop3 = pack2(sWo[3][ul], sWo[3][uh]);
    const u64 wop4 = pack2(sWo[4][ul], sWo[4][uh]);
    const float sh_lo = sSh[ul], sh_hi = sSh[uh];
    const u64 shp = pack2(sh_lo, sh_hi);

    const unsigned fbase = (unsigned)__cvta_generic_to_shared(&sF[w][0][0]);
    const float4* __restrict__ feat4 = reinterpret_cast<const float4*>(features);

    // ---- first pillar's loads ----
    int n = gw;
    float4 f4 = feat4[n * MPTS + lane];
    int np = num_points[n];
    int2 yx = *reinterpret_cast<const int2*>(coors + n * 4 + 2);  // {y, x}

    #pragma unroll 1
    for (int k = 0; k < PPW; k++) {
        // prefetch next pillar while processing this one
        float4 f4n; int npn; int2 yxn;
        if (k + 1 < PPW) {
            const int n2 = n + TOTWARPS;
            f4n = feat4[n2 * MPTS + lane];
            npn = num_points[n2];
            yxn = *reinterpret_cast<const int2*>(coors + n2 * 4 + 2);
        }

        // centroid sums via fixed-point integer warp reduction.
        // reference sums ALL 32 slots (incl. padded garbage), / np.
        const int ix = __float2int_rn(f4.x * FPSCALE);
        const int iy = __float2int_rn(f4.y * FPSCALE);
        const int iz = __float2int_rn(f4.z * FPSCALE);
        const int sxi = redux_add_s32(ix);
        const int syi = redux_add_s32(iy);
        const int szi = redux_add_s32(iz);

        // padded slots get point 0's coords -> over-read quads reproduce an
        // existing max candidate exactly (np >= 1 guaranteed)
        const float p0x = __shfl_sync(0xffffffffu, f4.x, 0);
        const float p0y = __shfl_sync(0xffffffffu, f4.y, 0);
        const float p0z = __shfl_sync(0xffffffffu, f4.z, 0);
        const float p0w = __shfl_sync(0xffffffffu, f4.w, 0);
        const bool valid = lane < np;
        sF[w][0][lane] = valid ? f4.x : p0x;
        sF[w][1][lane] = valid ? f4.y : p0y;
        sF[w][2][lane] = valid ? f4.z : p0z;
        sF[w][3][lane] = valid ? f4.w : p0w;
        __syncwarp();

        // negated means / offsets (bias consumed subtractively)
        const float nrnp = -INV_FPSCALE / (float)np;
        const float nmx = (float)sxi * nrnp;
        const float nmy = (float)syi * nrnp;
        const float nmz = (float)szi * nrnp;
        const float nox = fmaf((float)yx.y, -VX, -X_OFF);
        const float noy = fmaf((float)yx.x, -VY, -Y_OFF);

        // b (lo,hi) = sh - mx*W4 - my*W5 - mz*W6 - ox*W7 - oy*W8, packed chain
        u64 b2 = ffma2(pack2(nmx, nmx), wop0, shp);
        b2 = ffma2(pack2(nmy, nmy), wop1, b2);
        b2 = ffma2(pack2(nmz, nmz), wop2, b2);
        b2 = ffma2(pack2(nox, nox), wop3, b2);
        b2 = ffma2(pack2(noy, noy), wop4, b2);

        // raw max accumulators (bias added after the loop)
        float al0 = -3.4e38f, al1 = -3.4e38f, ah0 = -3.4e38f, ah1 = -3.4e38f;

        const int nq = (np + 3) >> 2;            // quads of points
        for (int j = 0; j < nq; j++) {
            const unsigned addr = fbase + j * 16;
            u64 x01, x23, y01, y23, z01, z23, q01, q23;
            lds2(x01, x23, addr);
            lds2(y01, y23, addr + 128);
            lds2(z01, z23, addr + 256);
            lds2(q01, q23, addr + 384);

            u64 v01l = fmul2(x01, w0l);
            u64 v23l = fmul2(x23, w0l);
            u64 v01h = fmul2(x01, w0h);
            u64 v23h = fmul2(x23, w0h);
            v01l = ffma2(y01, w1l, v01l);
            v23l = ffma2(y23, w1l, v23l);
            v01h = ffma2(y01, w1h, v01h);
            v23h = ffma2(y23, w1h, v23h);
            v01l = ffma2(z01, w2l, v01l);
            v23l = ffma2(z23, w2l, v23l);
            v01h = ffma2(z01, w2h, v01h);
            v23h = ffma2(z23, w2h, v23h);
            v01l = ffma2(q01, w3l, v01l);
            v23l = ffma2(q23, w3l, v23l);
            v01h = ffma2(q01, w3h, v01h);
            v23h = ffma2(q23, w3h, v23h);

            float a0, a1;
            unpack2(v01l, a0, a1); al0 = fmaxf(al0, a0); al1 = fmaxf(al1, a1);
            unpack2(v23l, a0, a1); al0 = fmaxf(al0, a0); al1 = fmaxf(al1, a1);
            unpack2(v01h, a0, a1); ah0 = fmaxf(ah0, a0); ah1 = fmaxf(ah1, a1);
            unpack2(v23h, a0, a1); ah0 = fmaxf(ah0, a0); ah1 = fmaxf(ah1, a1);
        }
        float b_lo, b_hi;
        unpack2(b2, b_lo, b_hi);
        float accl = fmaxf(al0, al1) + b_lo;
        float acch = fmaxf(ah0, ah1) + b_hi;
        // padded points contribute exactly `shift` when np < 32
        if (np < MPTS) {
            accl = fmaxf(accl, sh_lo);
            acch = fmaxf(acch, sh_hi);
        }
        accl = fmaxf(accl, 0.0f);   // relu after max (monotone)
        acch = fmaxf(acch, 0.0f);

        float* o = out + (size_t)n * 64;
        o[lane] = accl;                       // channels 0..31
        if (lane < 31) o[32 + lane] = acch;   // channels 32..62
        else           o[63] = (float)np;     // appended num_points

        __syncwarp();   // all lanes done with sF before next pillar overwrites
        n += TOTWARPS;
        f4 = f4n; np = npn; yx = yxn;
    }
}

extern "C" void kernel_launch(void* const* d_in, const int* in_sizes, int n_in,
                              void* d_out, int out_size)
{
    const float* features   = (const float*)d_in[0];
    const int*   num_points = (const int*)  d_in[1];
    const int*   coors      = (const int*)  d_in[2];
    const float* Wmat       = (const float*)d_in[3];
    const float* gamma_     = (const float*)d_in[4];
    const float* beta_      = (const float*)d_in[5];
    const float* rmean      = (const float*)d_in[6];
    const float* rvar       = (const float*)d_in[7];
    float*       out        = (float*)d_out;

    pfn_kernel<<<NBLOCKS, WPB * 32>>>(features, num_points, coors, Wmat,
                                      gamma_, beta_, rmean, rvar, out);
}